// round 12
// baseline (speedup 1.0000x reference)
#include <cuda_runtime.h>
#include <cuda_bf16.h>
#include <math.h>
#include <stdint.h>

#define B_ROWS 4096
#define NROWS  8192          // 2B
#define DDIM   1024
#define INV_T  10.0f
#define NTILE  64            // NROWS / 128

#define BK     32
#define BKP    40            // padded bf16 cols (80B row stride)
#define STAGES (DDIM / BK)   // 32
#define PIPE   5
#define BUFE   (128 * BKP)   // bf16 elems per operand per stage

// ---------------- device scratch ---------------------------------------------
__device__ __align__(128) __nv_bfloat16 g_reps[NROWS * DDIM];
__device__ float g_rowsum[NROWS];
__device__ float g_pos[NROWS];

// ---------------- helpers ------------------------------------------------------
__device__ __forceinline__ uint32_t smem_u32(const void* p) {
    uint32_t a;
    asm("{ .reg .u64 t; cvta.to.shared.u64 t, %1; cvt.u32.u64 %0, t; }" : "=r"(a) : "l"(p));
    return a;
}
__device__ __forceinline__ void cp16(uint32_t saddr, const void* gptr) {
    asm volatile("cp.async.cg.shared.global [%0], [%1], 16;" :: "r"(saddr), "l"(gptr) : "memory");
}
__device__ __forceinline__ void ldm_x4(uint32_t addr, uint32_t& r0, uint32_t& r1,
                                       uint32_t& r2, uint32_t& r3) {
    asm volatile("ldmatrix.sync.aligned.m8n8.x4.shared.b16 {%0,%1,%2,%3}, [%4];"
                 : "=r"(r0), "=r"(r1), "=r"(r2), "=r"(r3) : "r"(addr));
}
__device__ __forceinline__ void mma16816(float& d0, float& d1, float& d2, float& d3,
                                         uint32_t a0, uint32_t a1, uint32_t a2, uint32_t a3,
                                         uint32_t b0, uint32_t b1) {
    asm volatile(
        "mma.sync.aligned.m16n8k16.row.col.f32.bf16.bf16.f32 "
        "{%0,%1,%2,%3}, {%4,%5,%6,%7}, {%8,%9}, {%0,%1,%2,%3};"
        : "+f"(d0), "+f"(d1), "+f"(d2), "+f"(d3)
        : "r"(a0), "r"(a1), "r"(a2), "r"(a3), "r"(b0), "r"(b1));
}

// ---------------- kernel 1: row L2-normalize -> bf16 (MLP=4), zero rowsum -----
__global__ void normalize_kernel(const float* __restrict__ z1,
                                 const float* __restrict__ z2,
                                 float* __restrict__ out) {
    int row = blockIdx.x;
    const float* src = (row < B_ROWS) ? (z1 + (size_t)row * DDIM)
                                      : (z2 + (size_t)(row - B_ROWS) * DDIM);
    int t = threadIdx.x;                       // 64 threads, 4 float4 each
    float4 v0 = reinterpret_cast<const float4*>(src)[t];
    float4 v1 = reinterpret_cast<const float4*>(src)[t + 64];
    float4 v2 = reinterpret_cast<const float4*>(src)[t + 128];
    float4 v3 = reinterpret_cast<const float4*>(src)[t + 192];
    float s = v0.x * v0.x + v0.y * v0.y + v0.z * v0.z + v0.w * v0.w
            + v1.x * v1.x + v1.y * v1.y + v1.z * v1.z + v1.w * v1.w
            + v2.x * v2.x + v2.y * v2.y + v2.z * v2.z + v2.w * v2.w
            + v3.x * v3.x + v3.y * v3.y + v3.z * v3.z + v3.w * v3.w;

    __shared__ float sh[2];
    #pragma unroll
    for (int o = 16; o > 0; o >>= 1) s += __shfl_xor_sync(0xffffffffu, s, o);
    if ((t & 31) == 0) sh[t >> 5] = s;
    __syncthreads();
    float inv = 1.0f / fmaxf(sqrtf(sh[0] + sh[1]), 1e-12f);

    __nv_bfloat162* dst = reinterpret_cast<__nv_bfloat162*>(g_reps + (size_t)row * DDIM);
    dst[2 * t + 0] = __floats2bfloat162_rn(v0.x * inv, v0.y * inv);
    dst[2 * t + 1] = __floats2bfloat162_rn(v0.z * inv, v0.w * inv);
    dst[2 * (t + 64) + 0] = __floats2bfloat162_rn(v1.x * inv, v1.y * inv);
    dst[2 * (t + 64) + 1] = __floats2bfloat162_rn(v1.z * inv, v1.w * inv);
    dst[2 * (t + 128) + 0] = __floats2bfloat162_rn(v2.x * inv, v2.y * inv);
    dst[2 * (t + 128) + 1] = __floats2bfloat162_rn(v2.z * inv, v2.w * inv);
    dst[2 * (t + 192) + 0] = __floats2bfloat162_rn(v3.x * inv, v3.y * inv);
    dst[2 * (t + 192) + 1] = __floats2bfloat162_rn(v3.z * inv, v3.w * inv);
    if (t == 0) g_rowsum[row] = 0.0f;
    if (row == 0 && t == 0) out[0] = 0.0f;     // zero accumulator for loss kernel
}

// ---------------- kernel 2: HMMA GEMM (R5 shape; PIPE=5) ----------------------
extern __shared__ __nv_bfloat16 dsm[];   // [PIPE*BUFE] A, then [PIPE*BUFE] B

__global__ void __launch_bounds__(128, 2) simgemm_hmma() {
    int tid = threadIdx.x;
    int wid = tid >> 5;        // 0..3
    int lid = tid & 31;
    int wr = wid >> 1;         // 0..1 (M half)
    int wc = wid & 1;          // 0..1 (N half)

    // --- linear block id -> upper-triangle tile (I, J), J >= I ---
    int t = blockIdx.x;
    int I = (int)((129.0f - sqrtf(16641.0f - 8.0f * (float)t)) * 0.5f);
    if (I < 0) I = 0;
    if (I > NTILE - 1) I = NTILE - 1;
    while (I > 0 && I * (129 - I) / 2 > t) --I;
    while (I < NTILE - 1 && (I + 1) * (128 - I) / 2 <= t) ++I;
    int J = I + (t - I * (129 - I) / 2);
    int I0 = I * 128, J0 = J * 128;
    bool diag = (I == J);
    bool posTile = (J == I + 32);

    const __nv_bfloat16* gA = g_reps + (size_t)I0 * DDIM;
    const __nv_bfloat16* gB = g_reps + (size_t)J0 * DDIM;

    float acc[4][8][4];
    #pragma unroll
    for (int a = 0; a < 4; a++)
        #pragma unroll
        for (int b = 0; b < 8; b++)
            #pragma unroll
            for (int c = 0; c < 4; c++) acc[a][b][c] = 0.0f;

    // cp.async: 512 16B-chunks per operand per stage; 128 threads -> 4 each
    uint32_t chOff[4];
    int chRow[4], chCol[4];
    #pragma unroll
    for (int cc = 0; cc < 4; ++cc) {
        int ch = tid + cc * 128;
        chRow[cc] = ch >> 2;
        chCol[cc] = (ch & 3) << 3;
        chOff[cc] = (uint32_t)((chRow[cc] * BKP + chCol[cc]) * 2);
    }
    uint32_t aBufB[PIPE], bBufB[PIPE];
    #pragma unroll
    for (int b = 0; b < PIPE; b++) {
        aBufB[b] = smem_u32(&dsm[(size_t)b * BUFE]);
        bBufB[b] = smem_u32(&dsm[(size_t)(PIPE + b) * BUFE]);
    }

    // prologue: first PIPE-1 = 4 stages
    #pragma unroll
    for (int s = 0; s < PIPE - 1; ++s) {
        int k0 = s * BK;
        #pragma unroll
        for (int cc = 0; cc < 4; ++cc) {
            cp16(aBufB[s] + chOff[cc], gA + (size_t)chRow[cc] * DDIM + k0 + chCol[cc]);
            cp16(bBufB[s] + chOff[cc], gB + (size_t)chRow[cc] * DDIM + k0 + chCol[cc]);
        }
        asm volatile("cp.async.commit_group;" ::: "memory");
    }

    int aRow = wr * 64 + (lid & 15);
    int aColSel = (lid >> 4) << 3;
    int bRow = wc * 64 + (lid & 7) + ((lid >> 4) << 3);
    int bColSel = ((lid >> 3) & 1) << 3;

    int buf = 0, nbuf = PIPE - 1;   // nbuf: destination buffer for stage s+PIPE-1
    for (int s = 0; s < STAGES; ++s) {
        asm volatile("cp.async.wait_group %0;" :: "n"(PIPE - 2) : "memory");
        __syncthreads();

        {
            int sn = s + PIPE - 1;
            if (sn < STAGES) {
                int k0 = sn * BK;
                #pragma unroll
                for (int cc = 0; cc < 4; ++cc) {
                    cp16(aBufB[nbuf] + chOff[cc], gA + (size_t)chRow[cc] * DDIM + k0 + chCol[cc]);
                    cp16(bBufB[nbuf] + chOff[cc], gB + (size_t)chRow[cc] * DDIM + k0 + chCol[cc]);
                }
            }
            asm volatile("cp.async.commit_group;" ::: "memory");
        }

        #pragma unroll
        for (int ks = 0; ks < BK / 16; ++ks) {
            int kk = ks * 16;
            uint32_t a[4][4], b[4][4];
            #pragma unroll
            for (int mt = 0; mt < 4; ++mt) {
                uint32_t addr = aBufB[buf] + (uint32_t)(((aRow + mt * 16) * BKP + kk + aColSel) * 2);
                ldm_x4(addr, a[mt][0], a[mt][1], a[mt][2], a[mt][3]);
            }
            #pragma unroll
            for (int np = 0; np < 4; ++np) {
                uint32_t addr = bBufB[buf] + (uint32_t)(((bRow + np * 16) * BKP + kk + bColSel) * 2);
                ldm_x4(addr, b[np][0], b[np][1], b[np][2], b[np][3]);
            }
            #pragma unroll
            for (int mt = 0; mt < 4; ++mt)
                #pragma unroll
                for (int nt = 0; nt < 8; ++nt) {
                    uint32_t bb0 = (nt & 1) ? b[nt >> 1][2] : b[nt >> 1][0];
                    uint32_t bb1 = (nt & 1) ? b[nt >> 1][3] : b[nt >> 1][1];
                    mma16816(acc[mt][nt][0], acc[mt][nt][1], acc[mt][nt][2], acc[mt][nt][3],
                             a[mt][0], a[mt][1], a[mt][2], a[mt][3], bb0, bb1);
                }
        }

        if (++buf == PIPE) buf = 0;
        if (++nbuf == PIPE) nbuf = 0;
    }

    // --- epilogue ---------------------------------------------------------------
    int rBase = I0 + wr * 64;
    int cBase = J0 + wc * 64;
    float rowacc[4][2];
    float colacc[8][2];
    #pragma unroll
    for (int x = 0; x < 4; ++x) { rowacc[x][0] = rowacc[x][1] = 0.0f; }
    #pragma unroll
    for (int x = 0; x < 8; ++x) { colacc[x][0] = colacc[x][1] = 0.0f; }

    #pragma unroll
    for (int mt = 0; mt < 4; ++mt) {
        int i0 = rBase + mt * 16 + (lid >> 2);
        int i1 = i0 + 8;
        #pragma unroll
        for (int nt = 0; nt < 8; ++nt) {
            int j0 = cBase + nt * 8 + (lid & 3) * 2;
            int j1 = j0 + 1;
            float s00 = acc[mt][nt][0] * INV_T;
            float s01 = acc[mt][nt][1] * INV_T;
            float s10 = acc[mt][nt][2] * INV_T;
            float s11 = acc[mt][nt][3] * INV_T;
            if (posTile) {
                if (j0 == i0 + B_ROWS) { g_pos[i0] = s00; g_pos[j0] = s00; }
                if (j1 == i0 + B_ROWS) { g_pos[i0] = s01; g_pos[j1] = s01; }
                if (j0 == i1 + B_ROWS) { g_pos[i1] = s10; g_pos[j0] = s10; }
                if (j1 == i1 + B_ROWS) { g_pos[i1] = s11; g_pos[j1] = s11; }
            }
            float e00 = (diag && j0 == i0) ? 0.0f : __expf(s00);
            float e01 = (diag && j1 == i0) ? 0.0f : __expf(s01);
            float e10 = (diag && j0 == i1) ? 0.0f : __expf(s10);
            float e11 = (diag && j1 == i1) ? 0.0f : __expf(s11);
            rowacc[mt][0] += e00 + e01;
            rowacc[mt][1] += e10 + e11;
            colacc[nt][0] += e00 + e10;
            colacc[nt][1] += e01 + e11;
        }
    }

    #pragma unroll
    for (int mt = 0; mt < 4; ++mt) {
        float r0 = rowacc[mt][0], r1 = rowacc[mt][1];
        #pragma unroll
        for (int o = 1; o < 4; o <<= 1) {
            r0 += __shfl_xor_sync(0xffffffffu, r0, o);
            r1 += __shfl_xor_sync(0xffffffffu, r1, o);
        }
        if ((lid & 3) == 0) {
            int i0 = rBase + mt * 16 + (lid >> 2);
            atomicAdd(&g_rowsum[i0], r0);
            atomicAdd(&g_rowsum[i0 + 8], r1);
        }
    }

    if (!diag) {
        #pragma unroll
        for (int nt = 0; nt < 8; ++nt) {
            float cA = colacc[nt][0], cB = colacc[nt][1];
            #pragma unroll
            for (int o = 4; o < 32; o <<= 1) {
                cA += __shfl_xor_sync(0xffffffffu, cA, o);
                cB += __shfl_xor_sync(0xffffffffu, cB, o);
            }
            if (lid < 4) {
                int j0 = cBase + nt * 8 + lid * 2;
                atomicAdd(&g_rowsum[j0], cA);
                atomicAdd(&g_rowsum[j0 + 1], cB);
            }
        }
    }
}

// ---------------- kernel 3: distributed final loss (16 CTAs, 1 row/thread) ----
__global__ void loss_kernel(float* __restrict__ out) {
    int i = blockIdx.x * 512 + threadIdx.x;    // 16 * 512 = 8192 rows exactly
    float p = g_pos[i];
    float s = logf(expf(p) + g_rowsum[i]) - p;

    int t = threadIdx.x;
    __shared__ float sh[16];
    #pragma unroll
    for (int o = 16; o > 0; o >>= 1) s += __shfl_xor_sync(0xffffffffu, s, o);
    if ((t & 31) == 0) sh[t >> 5] = s;
    __syncthreads();
    if (t < 16) {
        float x = sh[t];
        #pragma unroll
        for (int o = 8; o > 0; o >>= 1) x += __shfl_xor_sync(0x0000ffffu, x, o);
        if (t == 0) atomicAdd(out, x / (float)NROWS);
    }
}

// ---------------- launcher ------------------------------------------------------
extern "C" void kernel_launch(void* const* d_in, const int* in_sizes, int n_in,
                              void* d_out, int out_size) {
    const float* z1 = (const float*)d_in[0];
    const float* z2 = (const float*)d_in[1];
    float* out = (float*)d_out;

    const int smemBytes = 2 * PIPE * BUFE * (int)sizeof(__nv_bfloat16);   // 102400
    cudaFuncSetAttribute(simgemm_hmma, cudaFuncAttributeMaxDynamicSharedMemorySize, smemBytes);

    normalize_kernel<<<NROWS, 64>>>(z1, z2, out);
    simgemm_hmma<<<NTILE * (NTILE + 1) / 2, 128, smemBytes>>>();
    loss_kernel<<<16, 512>>>(out);
}

// round 13
// speedup vs baseline: 1.0211x; 1.0211x over previous
#include <cuda_runtime.h>
#include <cuda_bf16.h>
#include <math.h>
#include <stdint.h>

#define B_ROWS 4096
#define NROWS  8192          // 2B
#define DDIM   1024
#define INV_T  10.0f
#define NTILE  64            // NROWS / 128

#define BK     32
#define BKP    40            // padded bf16 cols (80B row stride)
#define STAGES (DDIM / BK)   // 32
#define PIPE   4
#define BUFE   (128 * BKP)   // bf16 elems per operand per stage

// ---------------- device scratch ---------------------------------------------
__device__ __align__(128) __nv_bfloat16 g_reps[NROWS * DDIM];
__device__ float g_rowsum[NROWS];
__device__ float g_pos[NROWS];

// ---------------- helpers ------------------------------------------------------
__device__ __forceinline__ uint32_t smem_u32(const void* p) {
    uint32_t a;
    asm("{ .reg .u64 t; cvta.to.shared.u64 t, %1; cvt.u32.u64 %0, t; }" : "=r"(a) : "l"(p));
    return a;
}
__device__ __forceinline__ void cp16(uint32_t saddr, const void* gptr) {
    asm volatile("cp.async.cg.shared.global [%0], [%1], 16;" :: "r"(saddr), "l"(gptr) : "memory");
}
__device__ __forceinline__ void ldm_x4(uint32_t addr, uint32_t& r0, uint32_t& r1,
                                       uint32_t& r2, uint32_t& r3) {
    asm volatile("ldmatrix.sync.aligned.m8n8.x4.shared.b16 {%0,%1,%2,%3}, [%4];"
                 : "=r"(r0), "=r"(r1), "=r"(r2), "=r"(r3) : "r"(addr));
}
__device__ __forceinline__ void mma16816(float& d0, float& d1, float& d2, float& d3,
                                         uint32_t a0, uint32_t a1, uint32_t a2, uint32_t a3,
                                         uint32_t b0, uint32_t b1) {
    asm volatile(
        "mma.sync.aligned.m16n8k16.row.col.f32.bf16.bf16.f32 "
        "{%0,%1,%2,%3}, {%4,%5,%6,%7}, {%8,%9}, {%0,%1,%2,%3};"
        : "+f"(d0), "+f"(d1), "+f"(d2), "+f"(d3)
        : "r"(a0), "r"(a1), "r"(a2), "r"(a3), "r"(b0), "r"(b1));
}

// ---------------- kernel 1: warp-per-row L2-normalize -> bf16 (MLP=8) ---------
__global__ void __launch_bounds__(256) normalize_kernel(const float* __restrict__ z1,
                                                        const float* __restrict__ z2,
                                                        float* __restrict__ out) {
    int lane = threadIdx.x & 31;
    int warp = threadIdx.x >> 5;               // 0..7
    int row  = blockIdx.x * 8 + warp;          // 1024 blocks * 8 warps = 8192 rows
    const float* src = (row < B_ROWS) ? (z1 + (size_t)row * DDIM)
                                      : (z2 + (size_t)(row - B_ROWS) * DDIM);
    const float4* src4 = reinterpret_cast<const float4*>(src);

    float4 v[8];
    #pragma unroll
    for (int c = 0; c < 8; ++c) v[c] = src4[lane + 32 * c];

    float s = 0.0f;
    #pragma unroll
    for (int c = 0; c < 8; ++c)
        s += v[c].x * v[c].x + v[c].y * v[c].y + v[c].z * v[c].z + v[c].w * v[c].w;
    #pragma unroll
    for (int o = 16; o > 0; o >>= 1) s += __shfl_xor_sync(0xffffffffu, s, o);

    float inv = 1.0f / fmaxf(sqrtf(s), 1e-12f);

    __nv_bfloat162* dst = reinterpret_cast<__nv_bfloat162*>(g_reps + (size_t)row * DDIM);
    #pragma unroll
    for (int c = 0; c < 8; ++c) {
        int e = lane + 32 * c;
        dst[2 * e + 0] = __floats2bfloat162_rn(v[c].x * inv, v[c].y * inv);
        dst[2 * e + 1] = __floats2bfloat162_rn(v[c].z * inv, v[c].w * inv);
    }
    if (lane == 0) g_rowsum[row] = 0.0f;
    if (row == 0 && lane == 0) out[0] = 0.0f;  // zero accumulator for loss kernel
}

// ---------------- kernel 2: HMMA GEMM (R11 configuration, verbatim) -----------
extern __shared__ __nv_bfloat16 dsm[];   // [PIPE*BUFE] A, then [PIPE*BUFE] B

__global__ void __launch_bounds__(128, 2) simgemm_hmma() {
    int tid = threadIdx.x;
    int wid = tid >> 5;        // 0..3
    int lid = tid & 31;
    int wr = wid >> 1;         // 0..1 (M half)
    int wc = wid & 1;          // 0..1 (N half)

    // --- linear block id -> upper-triangle tile (I, J), J >= I ---
    int t = blockIdx.x;
    int I = (int)((129.0f - sqrtf(16641.0f - 8.0f * (float)t)) * 0.5f);
    if (I < 0) I = 0;
    if (I > NTILE - 1) I = NTILE - 1;
    while (I > 0 && I * (129 - I) / 2 > t) --I;
    while (I < NTILE - 1 && (I + 1) * (128 - I) / 2 <= t) ++I;
    int J = I + (t - I * (129 - I) / 2);
    int I0 = I * 128, J0 = J * 128;
    bool diag = (I == J);
    bool posTile = (J == I + 32);

    const __nv_bfloat16* gA = g_reps + (size_t)I0 * DDIM;
    const __nv_bfloat16* gB = g_reps + (size_t)J0 * DDIM;

    float acc[4][8][4];
    #pragma unroll
    for (int a = 0; a < 4; a++)
        #pragma unroll
        for (int b = 0; b < 8; b++)
            #pragma unroll
            for (int c = 0; c < 4; c++) acc[a][b][c] = 0.0f;

    // cp.async: 512 16B-chunks per operand per stage; 128 threads -> 4 each
    uint32_t chOff[4];
    int chRow[4], chCol[4];
    #pragma unroll
    for (int cc = 0; cc < 4; ++cc) {
        int ch = tid + cc * 128;
        chRow[cc] = ch >> 2;
        chCol[cc] = (ch & 3) << 3;
        chOff[cc] = (uint32_t)((chRow[cc] * BKP + chCol[cc]) * 2);
    }
    uint32_t aBufB[PIPE], bBufB[PIPE];
    #pragma unroll
    for (int b = 0; b < PIPE; b++) {
        aBufB[b] = smem_u32(&dsm[(size_t)b * BUFE]);
        bBufB[b] = smem_u32(&dsm[(size_t)(PIPE + b) * BUFE]);
    }

    // prologue
    #pragma unroll
    for (int s = 0; s < PIPE - 1; ++s) {
        int k0 = s * BK;
        #pragma unroll
        for (int cc = 0; cc < 4; ++cc) {
            cp16(aBufB[s] + chOff[cc], gA + (size_t)chRow[cc] * DDIM + k0 + chCol[cc]);
            cp16(bBufB[s] + chOff[cc], gB + (size_t)chRow[cc] * DDIM + k0 + chCol[cc]);
        }
        asm volatile("cp.async.commit_group;" ::: "memory");
    }

    int aRow = wr * 64 + (lid & 15);
    int aColSel = (lid >> 4) << 3;
    int bRow = wc * 64 + (lid & 7) + ((lid >> 4) << 3);
    int bColSel = ((lid >> 3) & 1) << 3;

    for (int s = 0; s < STAGES; ++s) {
        int buf = s & (PIPE - 1);
        asm volatile("cp.async.wait_group %0;" :: "n"(PIPE - 2) : "memory");
        __syncthreads();

        {
            int sn = s + PIPE - 1;
            if (sn < STAGES) {
                int nb = sn & (PIPE - 1);
                int k0 = sn * BK;
                #pragma unroll
                for (int cc = 0; cc < 4; ++cc) {
                    cp16(aBufB[nb] + chOff[cc], gA + (size_t)chRow[cc] * DDIM + k0 + chCol[cc]);
                    cp16(bBufB[nb] + chOff[cc], gB + (size_t)chRow[cc] * DDIM + k0 + chCol[cc]);
                }
            }
            asm volatile("cp.async.commit_group;" ::: "memory");
        }

        #pragma unroll
        for (int ks = 0; ks < BK / 16; ++ks) {
            int kk = ks * 16;
            uint32_t a[4][4], b[4][4];
            #pragma unroll
            for (int mt = 0; mt < 4; ++mt) {
                uint32_t addr = aBufB[buf] + (uint32_t)(((aRow + mt * 16) * BKP + kk + aColSel) * 2);
                ldm_x4(addr, a[mt][0], a[mt][1], a[mt][2], a[mt][3]);
            }
            #pragma unroll
            for (int np = 0; np < 4; ++np) {
                uint32_t addr = bBufB[buf] + (uint32_t)(((bRow + np * 16) * BKP + kk + bColSel) * 2);
                ldm_x4(addr, b[np][0], b[np][1], b[np][2], b[np][3]);
            }
            #pragma unroll
            for (int mt = 0; mt < 4; ++mt)
                #pragma unroll
                for (int nt = 0; nt < 8; ++nt) {
                    uint32_t bb0 = (nt & 1) ? b[nt >> 1][2] : b[nt >> 1][0];
                    uint32_t bb1 = (nt & 1) ? b[nt >> 1][3] : b[nt >> 1][1];
                    mma16816(acc[mt][nt][0], acc[mt][nt][1], acc[mt][nt][2], acc[mt][nt][3],
                             a[mt][0], a[mt][1], a[mt][2], a[mt][3], bb0, bb1);
                }
        }
    }

    // --- epilogue ---------------------------------------------------------------
    int rBase = I0 + wr * 64;
    int cBase = J0 + wc * 64;
    float rowacc[4][2];
    float colacc[8][2];
    #pragma unroll
    for (int x = 0; x < 4; ++x) { rowacc[x][0] = rowacc[x][1] = 0.0f; }
    #pragma unroll
    for (int x = 0; x < 8; ++x) { colacc[x][0] = colacc[x][1] = 0.0f; }

    #pragma unroll
    for (int mt = 0; mt < 4; ++mt) {
        int i0 = rBase + mt * 16 + (lid >> 2);
        int i1 = i0 + 8;
        #pragma unroll
        for (int nt = 0; nt < 8; ++nt) {
            int j0 = cBase + nt * 8 + (lid & 3) * 2;
            int j1 = j0 + 1;
            float s00 = acc[mt][nt][0] * INV_T;
            float s01 = acc[mt][nt][1] * INV_T;
            float s10 = acc[mt][nt][2] * INV_T;
            float s11 = acc[mt][nt][3] * INV_T;
            if (posTile) {
                if (j0 == i0 + B_ROWS) { g_pos[i0] = s00; g_pos[j0] = s00; }
                if (j1 == i0 + B_ROWS) { g_pos[i0] = s01; g_pos[j1] = s01; }
                if (j0 == i1 + B_ROWS) { g_pos[i1] = s10; g_pos[j0] = s10; }
                if (j1 == i1 + B_ROWS) { g_pos[i1] = s11; g_pos[j1] = s11; }
            }
            float e00 = (diag && j0 == i0) ? 0.0f : __expf(s00);
            float e01 = (diag && j1 == i0) ? 0.0f : __expf(s01);
            float e10 = (diag && j0 == i1) ? 0.0f : __expf(s10);
            float e11 = (diag && j1 == i1) ? 0.0f : __expf(s11);
            rowacc[mt][0] += e00 + e01;
            rowacc[mt][1] += e10 + e11;
            colacc[nt][0] += e00 + e10;
            colacc[nt][1] += e01 + e11;
        }
    }

    #pragma unroll
    for (int mt = 0; mt < 4; ++mt) {
        float r0 = rowacc[mt][0], r1 = rowacc[mt][1];
        #pragma unroll
        for (int o = 1; o < 4; o <<= 1) {
            r0 += __shfl_xor_sync(0xffffffffu, r0, o);
            r1 += __shfl_xor_sync(0xffffffffu, r1, o);
        }
        if ((lid & 3) == 0) {
            int i0 = rBase + mt * 16 + (lid >> 2);
            atomicAdd(&g_rowsum[i0], r0);
            atomicAdd(&g_rowsum[i0 + 8], r1);
        }
    }

    if (!diag) {
        #pragma unroll
        for (int nt = 0; nt < 8; ++nt) {
            float cA = colacc[nt][0], cB = colacc[nt][1];
            #pragma unroll
            for (int o = 4; o < 32; o <<= 1) {
                cA += __shfl_xor_sync(0xffffffffu, cA, o);
                cB += __shfl_xor_sync(0xffffffffu, cB, o);
            }
            if (lid < 4) {
                int j0 = cBase + nt * 8 + lid * 2;
                atomicAdd(&g_rowsum[j0], cA);
                atomicAdd(&g_rowsum[j0 + 1], cB);
            }
        }
    }
}

// ---------------- kernel 3: distributed final loss (16 CTAs, 1 row/thread) ----
__global__ void loss_kernel(float* __restrict__ out) {
    int i = blockIdx.x * 512 + threadIdx.x;    // 16 * 512 = 8192 rows exactly
    float p = g_pos[i];
    float s = logf(expf(p) + g_rowsum[i]) - p;

    int t = threadIdx.x;
    __shared__ float sh[16];
    #pragma unroll
    for (int o = 16; o > 0; o >>= 1) s += __shfl_xor_sync(0xffffffffu, s, o);
    if ((t & 31) == 0) sh[t >> 5] = s;
    __syncthreads();
    if (t < 16) {
        float x = sh[t];
        #pragma unroll
        for (int o = 8; o > 0; o >>= 1) x += __shfl_xor_sync(0x0000ffffu, x, o);
        if (t == 0) atomicAdd(out, x / (float)NROWS);
    }
}

// ---------------- launcher ------------------------------------------------------
extern "C" void kernel_launch(void* const* d_in, const int* in_sizes, int n_in,
                              void* d_out, int out_size) {
    const float* z1 = (const float*)d_in[0];
    const float* z2 = (const float*)d_in[1];
    float* out = (float*)d_out;

    const int smemBytes = 2 * PIPE * BUFE * (int)sizeof(__nv_bfloat16);   // 81920
    cudaFuncSetAttribute(simgemm_hmma, cudaFuncAttributeMaxDynamicSharedMemorySize, smemBytes);

    normalize_kernel<<<NROWS / 8, 256>>>(z1, z2, out);
    simgemm_hmma<<<NTILE * (NTILE + 1) / 2, 128, smemBytes>>>();
    loss_kernel<<<16, 512>>>(out);
}

// round 14
// speedup vs baseline: 1.0247x; 1.0036x over previous
#include <cuda_runtime.h>
#include <cuda_bf16.h>
#include <math.h>
#include <stdint.h>

#define B_ROWS 4096
#define NROWS  8192          // 2B
#define DDIM   1024
#define INV_T  10.0f
#define NTILE  64            // NROWS / 128

#define BK     32
#define BKP    40            // padded bf16 cols (80B row stride)
#define STAGES (DDIM / BK)   // 32
#define PIPE   4
#define BUFE   (128 * BKP)   // bf16 elems per operand per stage

// ---------------- device scratch ---------------------------------------------
__device__ __align__(128) __nv_bfloat16 g_reps[NROWS * DDIM];
__device__ float g_rowsum[NROWS];
__device__ float g_pos[NROWS];

// ---------------- helpers ------------------------------------------------------
__device__ __forceinline__ uint32_t smem_u32(const void* p) {
    uint32_t a;
    asm("{ .reg .u64 t; cvta.to.shared.u64 t, %1; cvt.u32.u64 %0, t; }" : "=r"(a) : "l"(p));
    return a;
}
__device__ __forceinline__ void cp16(uint32_t saddr, const void* gptr) {
    asm volatile("cp.async.cg.shared.global [%0], [%1], 16;" :: "r"(saddr), "l"(gptr) : "memory");
}
__device__ __forceinline__ void ldm_x4(uint32_t addr, uint32_t& r0, uint32_t& r1,
                                       uint32_t& r2, uint32_t& r3) {
    asm volatile("ldmatrix.sync.aligned.m8n8.x4.shared.b16 {%0,%1,%2,%3}, [%4];"
                 : "=r"(r0), "=r"(r1), "=r"(r2), "=r"(r3) : "r"(addr));
}
__device__ __forceinline__ void mma16816(float& d0, float& d1, float& d2, float& d3,
                                         uint32_t a0, uint32_t a1, uint32_t a2, uint32_t a3,
                                         uint32_t b0, uint32_t b1) {
    asm volatile(
        "mma.sync.aligned.m16n8k16.row.col.f32.bf16.bf16.f32 "
        "{%0,%1,%2,%3}, {%4,%5,%6,%7}, {%8,%9}, {%0,%1,%2,%3};"
        : "+f"(d0), "+f"(d1), "+f"(d2), "+f"(d3)
        : "r"(a0), "r"(a1), "r"(a2), "r"(a3), "r"(b0), "r"(b1));
}

// ---------------- kernel 1: warp-per-row normalize, two-phase (L2 re-read) ----
__global__ void __launch_bounds__(128) normalize_kernel(const float* __restrict__ z1,
                                                        const float* __restrict__ z2,
                                                        float* __restrict__ out) {
    int lane = threadIdx.x & 31;
    int warp = threadIdx.x >> 5;               // 0..3
    int row  = blockIdx.x * 4 + warp;          // 2048 blocks * 4 warps = 8192 rows
    const float* src = (row < B_ROWS) ? (z1 + (size_t)row * DDIM)
                                      : (z2 + (size_t)(row - B_ROWS) * DDIM);
    const float4* src4 = reinterpret_cast<const float4*>(src);

    // phase 1: stream row, sum of squares (values die immediately -> low regs)
    float s = 0.0f;
    #pragma unroll
    for (int c = 0; c < 8; ++c) {
        float4 v = src4[lane + 32 * c];
        s += v.x * v.x + v.y * v.y + v.z * v.z + v.w * v.w;
    }
    #pragma unroll
    for (int o = 16; o > 0; o >>= 1) s += __shfl_xor_sync(0xffffffffu, s, o);
    float inv = 1.0f / fmaxf(sqrtf(s), 1e-12f);

    // phase 2: re-read (L2 hits), convert to bf16, write
    __nv_bfloat162* dst = reinterpret_cast<__nv_bfloat162*>(g_reps + (size_t)row * DDIM);
    #pragma unroll
    for (int c = 0; c < 8; ++c) {
        int e = lane + 32 * c;
        float4 v = src4[e];
        dst[2 * e + 0] = __floats2bfloat162_rn(v.x * inv, v.y * inv);
        dst[2 * e + 1] = __floats2bfloat162_rn(v.z * inv, v.w * inv);
    }
    if (lane == 0) g_rowsum[row] = 0.0f;
    if (row == 0 && lane == 0) out[0] = 0.0f;  // zero accumulator for loss kernel
}

// ---------------- kernel 2: HMMA GEMM (R11/R13 configuration, verbatim) -------
extern __shared__ __nv_bfloat16 dsm[];   // [PIPE*BUFE] A, then [PIPE*BUFE] B

__global__ void __launch_bounds__(128, 2) simgemm_hmma() {
    int tid = threadIdx.x;
    int wid = tid >> 5;        // 0..3
    int lid = tid & 31;
    int wr = wid >> 1;         // 0..1 (M half)
    int wc = wid & 1;          // 0..1 (N half)

    // --- linear block id -> upper-triangle tile (I, J), J >= I ---
    int t = blockIdx.x;
    int I = (int)((129.0f - sqrtf(16641.0f - 8.0f * (float)t)) * 0.5f);
    if (I < 0) I = 0;
    if (I > NTILE - 1) I = NTILE - 1;
    while (I > 0 && I * (129 - I) / 2 > t) --I;
    while (I < NTILE - 1 && (I + 1) * (128 - I) / 2 <= t) ++I;
    int J = I + (t - I * (129 - I) / 2);
    int I0 = I * 128, J0 = J * 128;
    bool diag = (I == J);
    bool posTile = (J == I + 32);

    const __nv_bfloat16* gA = g_reps + (size_t)I0 * DDIM;
    const __nv_bfloat16* gB = g_reps + (size_t)J0 * DDIM;

    float acc[4][8][4];
    #pragma unroll
    for (int a = 0; a < 4; a++)
        #pragma unroll
        for (int b = 0; b < 8; b++)
            #pragma unroll
            for (int c = 0; c < 4; c++) acc[a][b][c] = 0.0f;

    // cp.async: 512 16B-chunks per operand per stage; 128 threads -> 4 each
    uint32_t chOff[4];
    int chRow[4], chCol[4];
    #pragma unroll
    for (int cc = 0; cc < 4; ++cc) {
        int ch = tid + cc * 128;
        chRow[cc] = ch >> 2;
        chCol[cc] = (ch & 3) << 3;
        chOff[cc] = (uint32_t)((chRow[cc] * BKP + chCol[cc]) * 2);
    }
    uint32_t aBufB[PIPE], bBufB[PIPE];
    #pragma unroll
    for (int b = 0; b < PIPE; b++) {
        aBufB[b] = smem_u32(&dsm[(size_t)b * BUFE]);
        bBufB[b] = smem_u32(&dsm[(size_t)(PIPE + b) * BUFE]);
    }

    // prologue
    #pragma unroll
    for (int s = 0; s < PIPE - 1; ++s) {
        int k0 = s * BK;
        #pragma unroll
        for (int cc = 0; cc < 4; ++cc) {
            cp16(aBufB[s] + chOff[cc], gA + (size_t)chRow[cc] * DDIM + k0 + chCol[cc]);
            cp16(bBufB[s] + chOff[cc], gB + (size_t)chRow[cc] * DDIM + k0 + chCol[cc]);
        }
        asm volatile("cp.async.commit_group;" ::: "memory");
    }

    int aRow = wr * 64 + (lid & 15);
    int aColSel = (lid >> 4) << 3;
    int bRow = wc * 64 + (lid & 7) + ((lid >> 4) << 3);
    int bColSel = ((lid >> 3) & 1) << 3;

    for (int s = 0; s < STAGES; ++s) {
        int buf = s & (PIPE - 1);
        asm volatile("cp.async.wait_group %0;" :: "n"(PIPE - 2) : "memory");
        __syncthreads();

        {
            int sn = s + PIPE - 1;
            if (sn < STAGES) {
                int nb = sn & (PIPE - 1);
                int k0 = sn * BK;
                #pragma unroll
                for (int cc = 0; cc < 4; ++cc) {
                    cp16(aBufB[nb] + chOff[cc], gA + (size_t)chRow[cc] * DDIM + k0 + chCol[cc]);
                    cp16(bBufB[nb] + chOff[cc], gB + (size_t)chRow[cc] * DDIM + k0 + chCol[cc]);
                }
            }
            asm volatile("cp.async.commit_group;" ::: "memory");
        }

        #pragma unroll
        for (int ks = 0; ks < BK / 16; ++ks) {
            int kk = ks * 16;
            uint32_t a[4][4], b[4][4];
            #pragma unroll
            for (int mt = 0; mt < 4; ++mt) {
                uint32_t addr = aBufB[buf] + (uint32_t)(((aRow + mt * 16) * BKP + kk + aColSel) * 2);
                ldm_x4(addr, a[mt][0], a[mt][1], a[mt][2], a[mt][3]);
            }
            #pragma unroll
            for (int np = 0; np < 4; ++np) {
                uint32_t addr = bBufB[buf] + (uint32_t)(((bRow + np * 16) * BKP + kk + bColSel) * 2);
                ldm_x4(addr, b[np][0], b[np][1], b[np][2], b[np][3]);
            }
            #pragma unroll
            for (int mt = 0; mt < 4; ++mt)
                #pragma unroll
                for (int nt = 0; nt < 8; ++nt) {
                    uint32_t bb0 = (nt & 1) ? b[nt >> 1][2] : b[nt >> 1][0];
                    uint32_t bb1 = (nt & 1) ? b[nt >> 1][3] : b[nt >> 1][1];
                    mma16816(acc[mt][nt][0], acc[mt][nt][1], acc[mt][nt][2], acc[mt][nt][3],
                             a[mt][0], a[mt][1], a[mt][2], a[mt][3], bb0, bb1);
                }
        }
    }

    // --- epilogue ---------------------------------------------------------------
    int rBase = I0 + wr * 64;
    int cBase = J0 + wc * 64;
    float rowacc[4][2];
    float colacc[8][2];
    #pragma unroll
    for (int x = 0; x < 4; ++x) { rowacc[x][0] = rowacc[x][1] = 0.0f; }
    #pragma unroll
    for (int x = 0; x < 8; ++x) { colacc[x][0] = colacc[x][1] = 0.0f; }

    #pragma unroll
    for (int mt = 0; mt < 4; ++mt) {
        int i0 = rBase + mt * 16 + (lid >> 2);
        int i1 = i0 + 8;
        #pragma unroll
        for (int nt = 0; nt < 8; ++nt) {
            int j0 = cBase + nt * 8 + (lid & 3) * 2;
            int j1 = j0 + 1;
            float s00 = acc[mt][nt][0] * INV_T;
            float s01 = acc[mt][nt][1] * INV_T;
            float s10 = acc[mt][nt][2] * INV_T;
            float s11 = acc[mt][nt][3] * INV_T;
            if (posTile) {
                if (j0 == i0 + B_ROWS) { g_pos[i0] = s00; g_pos[j0] = s00; }
                if (j1 == i0 + B_ROWS) { g_pos[i0] = s01; g_pos[j1] = s01; }
                if (j0 == i1 + B_ROWS) { g_pos[i1] = s10; g_pos[j0] = s10; }
                if (j1 == i1 + B_ROWS) { g_pos[i1] = s11; g_pos[j1] = s11; }
            }
            float e00 = (diag && j0 == i0) ? 0.0f : __expf(s00);
            float e01 = (diag && j1 == i0) ? 0.0f : __expf(s01);
            float e10 = (diag && j0 == i1) ? 0.0f : __expf(s10);
            float e11 = (diag && j1 == i1) ? 0.0f : __expf(s11);
            rowacc[mt][0] += e00 + e01;
            rowacc[mt][1] += e10 + e11;
            colacc[nt][0] += e00 + e10;
            colacc[nt][1] += e01 + e11;
        }
    }

    #pragma unroll
    for (int mt = 0; mt < 4; ++mt) {
        float r0 = rowacc[mt][0], r1 = rowacc[mt][1];
        #pragma unroll
        for (int o = 1; o < 4; o <<= 1) {
            r0 += __shfl_xor_sync(0xffffffffu, r0, o);
            r1 += __shfl_xor_sync(0xffffffffu, r1, o);
        }
        if ((lid & 3) == 0) {
            int i0 = rBase + mt * 16 + (lid >> 2);
            atomicAdd(&g_rowsum[i0], r0);
            atomicAdd(&g_rowsum[i0 + 8], r1);
        }
    }

    if (!diag) {
        #pragma unroll
        for (int nt = 0; nt < 8; ++nt) {
            float cA = colacc[nt][0], cB = colacc[nt][1];
            #pragma unroll
            for (int o = 4; o < 32; o <<= 1) {
                cA += __shfl_xor_sync(0xffffffffu, cA, o);
                cB += __shfl_xor_sync(0xffffffffu, cB, o);
            }
            if (lid < 4) {
                int j0 = cBase + nt * 8 + lid * 2;
                atomicAdd(&g_rowsum[j0], cA);
                atomicAdd(&g_rowsum[j0 + 1], cB);
            }
        }
    }
}

// ---------------- kernel 3: distributed final loss (16 CTAs, 1 row/thread) ----
__global__ void loss_kernel(float* __restrict__ out) {
    int i = blockIdx.x * 512 + threadIdx.x;    // 16 * 512 = 8192 rows exactly
    float p = g_pos[i];
    float s = logf(expf(p) + g_rowsum[i]) - p;

    int t = threadIdx.x;
    __shared__ float sh[16];
    #pragma unroll
    for (int o = 16; o > 0; o >>= 1) s += __shfl_xor_sync(0xffffffffu, s, o);
    if ((t & 31) == 0) sh[t >> 5] = s;
    __syncthreads();
    if (t < 16) {
        float x = sh[t];
        #pragma unroll
        for (int o = 8; o > 0; o >>= 1) x += __shfl_xor_sync(0x0000ffffu, x, o);
        if (t == 0) atomicAdd(out, x / (float)NROWS);
    }
}

// ---------------- launcher ------------------------------------------------------
extern "C" void kernel_launch(void* const* d_in, const int* in_sizes, int n_in,
                              void* d_out, int out_size) {
    const float* z1 = (const float*)d_in[0];
    const float* z2 = (const float*)d_in[1];
    float* out = (float*)d_out;

    const int smemBytes = 2 * PIPE * BUFE * (int)sizeof(__nv_bfloat16);   // 81920
    cudaFuncSetAttribute(simgemm_hmma, cudaFuncAttributeMaxDynamicSharedMemorySize, smemBytes);

    normalize_kernel<<<NROWS / 4, 128>>>(z1, z2, out);
    simgemm_hmma<<<NTILE * (NTILE + 1) / 2, 128, smemBytes>>>();
    loss_kernel<<<16, 512>>>(out);
}